// round 15
// baseline (speedup 1.0000x reference)
#include <cuda_runtime.h>
#include <cuda_bf16.h>
#include <cuda_fp16.h>
#include <math.h>
#include <stdint.h>

// Problem shape constants
#define BB 8
#define LL 512
#define NN 2048
#define CC 1024
#define DD 128

// ---------------------------------------------------------------------------
// Scratch (device globals — no allocations allowed)
// ---------------------------------------------------------------------------
__device__ __align__(16) __nv_bfloat16 g_feat_h[BB * NN * CC];   // 32 MB
__device__ __align__(16) __nv_bfloat16 g_feat_l[BB * NN * CC];
__device__ __align__(16) __half        g_log_h[BB * LL * NN];    // fp16 hi only
__device__ __align__(16) __nv_bfloat16 g_wq_h[DD * CC];
__device__ __align__(16) __nv_bfloat16 g_wq_l[DD * CC];
__device__ __align__(16) __nv_bfloat16 g_wk_h[DD * CC];
__device__ __align__(16) __nv_bfloat16 g_wk_l[DD * CC];
__device__ __align__(16) __nv_bfloat16 g_q_h[BB * NN * DD];      // 4 MB
__device__ __align__(16) __nv_bfloat16 g_q_l[BB * NN * DD];
__device__ __align__(16) __nv_bfloat16 g_k_h[BB * NN * DD];
__device__ __align__(16) __nv_bfloat16 g_k_l[BB * NN * DD];
__device__ __align__(16) float g_energy[(size_t)BB * NN * NN];   // 128 MB
__device__ __align__(16) __half g_attn[(size_t)BB * NN * NN];    // 64 MB fp16

// ---------------------------------------------------------------------------
// Helpers (family-portable PTX only: ldmatrix / mma.sync / cp.async)
// ---------------------------------------------------------------------------
__device__ __forceinline__ uint32_t smem_u32(const void* p) {
    uint32_t a;
    asm("{ .reg .u64 t; cvta.to.shared.u64 t, %1; cvt.u32.u64 %0, t; }"
        : "=r"(a) : "l"(p));
    return a;
}

__device__ __forceinline__ void ldm_x4(uint32_t r[4], uint32_t addr) {
    asm volatile("ldmatrix.sync.aligned.m8n8.x4.shared.b16 {%0,%1,%2,%3}, [%4];"
                 : "=r"(r[0]), "=r"(r[1]), "=r"(r[2]), "=r"(r[3])
                 : "r"(addr));
}

__device__ __forceinline__ void mma_bf16(float d[4], const uint32_t a[4],
                                         uint32_t b0, uint32_t b1) {
    asm volatile(
        "mma.sync.aligned.m16n8k16.row.col.f32.bf16.bf16.f32 "
        "{%0,%1,%2,%3}, {%4,%5,%6,%7}, {%8,%9}, {%0,%1,%2,%3};"
        : "+f"(d[0]), "+f"(d[1]), "+f"(d[2]), "+f"(d[3])
        : "r"(a[0]), "r"(a[1]), "r"(a[2]), "r"(a[3]), "r"(b0), "r"(b1));
}

__device__ __forceinline__ void mma_f16(float d[4], const uint32_t a[4],
                                        uint32_t b0, uint32_t b1) {
    asm volatile(
        "mma.sync.aligned.m16n8k16.row.col.f32.f16.f16.f32 "
        "{%0,%1,%2,%3}, {%4,%5,%6,%7}, {%8,%9}, {%0,%1,%2,%3};"
        : "+f"(d[0]), "+f"(d[1]), "+f"(d[2]), "+f"(d[3])
        : "r"(a[0]), "r"(a[1]), "r"(a[2]), "r"(a[3]), "r"(b0), "r"(b1));
}

__device__ __forceinline__ void cpa16(uint32_t dst, const void* src) {
    asm volatile("cp.async.cg.shared.global [%0], [%1], 16;"
                 :: "r"(dst), "l"(src));
}
__device__ __forceinline__ void cp_commit() {
    asm volatile("cp.async.commit_group;" ::: "memory");
}
template <int N>
__device__ __forceinline__ void cp_wait() {
    asm volatile("cp.async.wait_group %0;" :: "n"(N) : "memory");
}

__device__ __forceinline__ uint32_t sw128(uint32_t off) {
    return off ^ ((off >> 3) & 0x70);
}

// Fast split fp32 -> (bf16 hi rtz, bf16 lo rn) packed pairs.
__device__ __forceinline__ void split2(float x0, float x1, uint32_t& hi, uint32_t& lo) {
    const uint32_t xi0 = __float_as_uint(x0);
    const uint32_t xi1 = __float_as_uint(x1);
    asm("prmt.b32 %0, %1, %2, 0x7632;" : "=r"(hi) : "r"(xi0), "r"(xi1));
    const float t0 = __uint_as_float(xi0 & 0xFFFF0000u);
    const float t1 = __uint_as_float(xi1 & 0xFFFF0000u);
    const float l0 = x0 - t0;
    const float l1 = x1 - t1;
    asm("cvt.rn.bf16x2.f32 %0, %1, %2;" : "=r"(lo) : "f"(l1), "f"(l0));
}

// ---------------------------------------------------------------------------
// Merged elementwise split: feat/Wq/Wk -> bf16 hi/lo ; logits -> fp16 (hi only)
// ---------------------------------------------------------------------------
#define F4C (BB * NN * CC / 4)
#define L4C (BB * LL * NN / 4)
#define W4C (DD * CC / 4)

__global__ __launch_bounds__(256) void split_all_kernel(
    const float4* __restrict__ feat, const float4* __restrict__ logi,
    const float4* __restrict__ wq,   const float4* __restrict__ wk,
    uint2* __restrict__ fh, uint2* __restrict__ fl,
    uint2* __restrict__ lh,
    uint2* __restrict__ qh, uint2* __restrict__ ql,
    uint2* __restrict__ kh, uint2* __restrict__ kl)
{
    const int i = blockIdx.x * 256 + threadIdx.x;
    uint32_t h0, l0, h1, l1;
    if (i < F4C) {
        float4 v = feat[i];
        split2(v.x, v.y, h0, l0); split2(v.z, v.w, h1, l1);
        fh[i] = make_uint2(h0, h1); fl[i] = make_uint2(l0, l1);
    } else if (i < F4C + L4C) {
        const int j = i - F4C;
        float4 v = logi[j];
        asm("cvt.rn.f16x2.f32 %0, %1, %2;" : "=r"(h0) : "f"(v.y), "f"(v.x));
        asm("cvt.rn.f16x2.f32 %0, %1, %2;" : "=r"(h1) : "f"(v.w), "f"(v.z));
        lh[j] = make_uint2(h0, h1);
    } else if (i < F4C + L4C + W4C) {
        const int j = i - F4C - L4C;
        float4 v = wq[j];
        split2(v.x, v.y, h0, l0); split2(v.z, v.w, h1, l1);
        qh[j] = make_uint2(h0, h1); ql[j] = make_uint2(l0, l1);
    } else {
        const int j = i - F4C - L4C - W4C;
        float4 v = wk[j];
        split2(v.x, v.y, h0, l0); split2(v.z, v.w, h1, l1);
        kh[j] = make_uint2(h0, h1); kl[j] = make_uint2(l0, l1);
    }
}

// ---------------------------------------------------------------------------
// bf16 HMMA NT GEMM, 3-term split (proj + energy).
// CHUNK=32 (SW64 rows), 3 stages, 96KB -> 2 CTAs/SM via launch_bounds(256,2).
// 256 threads = 8 warps (4m x 2n), warp tile 32x64.
// Dual-B mode (Bh2 != 0): blockIdx.x selects {B,C,bias} set, n0 = 0.
// ---------------------------------------------------------------------------
template <int CHUNK>
__device__ __forceinline__ uint32_t swz(uint32_t off) {
    if (CHUNK == 64) return off ^ ((off >> 3) & 0x70);   // SW128 (128B rows)
    else             return off ^ ((off >> 3) & 0x30);   // SW64  (64B rows)
}

template <int CHUNK>
__device__ __forceinline__ void fill_stage(uint32_t st,
    const __nv_bfloat16* __restrict__ ah, const __nv_bfloat16* __restrict__ al,
    const __nv_bfloat16* __restrict__ bh, const __nv_bfloat16* __restrict__ bl,
    int K, int tid)
{
    constexpr int ROWB = CHUNK * 2;          // bytes per smem row
    constexpr int MATB = 128 * ROWB;         // bytes per matrix tile
    constexpr int G    = CHUNK / 8;          // 16B groups per row
    constexpr int ITER = CHUNK / 16;         // 128*G/256 per-thread loads/matrix
    #pragma unroll
    for (int i = 0; i < ITER; ++i) {
        const int id  = tid + (i << 8);
        const int row = id / G, g = id % G;
        const long long goff = (long long)row * K + (g << 3);
        const uint32_t so = swz<CHUNK>((uint32_t)(row * ROWB + (g << 4)));
        cpa16(st + so,            ah + goff);
        cpa16(st + MATB + so,     al + goff);
        cpa16(st + 2 * MATB + so, bh + goff);
        cpa16(st + 3 * MATB + so, bl + goff);
    }
    cp_commit();
}

#define CH32 32
#define STB32 (4 * 128 * (CH32 * 2))        // 32768
#define SM32  (3 * STB32)                   // 98304

__global__ __launch_bounds__(256, 2) void hgemm_nt(
    const __nv_bfloat16* __restrict__ Ah, const __nv_bfloat16* __restrict__ Al,
    const __nv_bfloat16* __restrict__ pBh, const __nv_bfloat16* __restrict__ pBl,
    const __nv_bfloat16* __restrict__ Bh2, const __nv_bfloat16* __restrict__ Bl2,
    float* __restrict__ Cf,
    __nv_bfloat16* __restrict__ pCh, __nv_bfloat16* __restrict__ pCl,
    __nv_bfloat16* __restrict__ Ch2, __nv_bfloat16* __restrict__ Cl2,
    const float* __restrict__ pbias, const float* __restrict__ bias2,
    int M, int N, int K,
    long long sA, long long sB, long long sC)
{
    constexpr int ROWB = CH32 * 2;          // 64
    constexpr int MATB = 128 * ROWB;        // 8192
    constexpr int KS   = CH32 / 16;         // 2

    extern __shared__ char smem[];
    const uint32_t sbase = smem_u32(smem);
    const int tid  = threadIdx.x;
    const int lane = tid & 31;
    const int wid  = tid >> 5;

    const int bz = blockIdx.z;
    const int m0 = blockIdx.y * 128;

    const __nv_bfloat16* Bh = pBh;
    const __nv_bfloat16* Bl = pBl;
    __nv_bfloat16* Ch = pCh;
    __nv_bfloat16* Cl = pCl;
    const float* bias = pbias;
    int n0;
    if (Bh2) {
        n0 = 0;
        if (blockIdx.x) { Bh = Bh2; Bl = Bl2; Ch = Ch2; Cl = Cl2; bias = bias2; }
    } else {
        n0 = blockIdx.x * 128;
    }

    const __nv_bfloat16* Aht = Ah + bz * sA + (long long)m0 * K;
    const __nv_bfloat16* Alt = Al + bz * sA + (long long)m0 * K;
    const __nv_bfloat16* Bht = Bh + bz * sB + (long long)n0 * K;
    const __nv_bfloat16* Blt = Bl + bz * sB + (long long)n0 * K;

    const int wm = (wid & 3) * 32;
    const int wn = (wid >> 2) * 64;
    const int qq = lane >> 3;
    const int rr = lane & 7;

    float acc[2][8][4];
    #pragma unroll
    for (int mi = 0; mi < 2; mi++)
        #pragma unroll
        for (int ni = 0; ni < 8; ni++)
            #pragma unroll
            for (int c = 0; c < 4; c++) acc[mi][ni][c] = 0.0f;

    const int nch = K / CH32;

    fill_stage<CH32>(sbase, Aht, Alt, Bht, Blt, K, tid);
    fill_stage<CH32>(sbase + STB32, Aht + CH32, Alt + CH32,
                     Bht + CH32, Blt + CH32, K, tid);

    for (int it = 0; it < nch; ++it) {
        if (it + 1 < nch) cp_wait<1>(); else cp_wait<0>();
        __syncthreads();

        const uint32_t st = sbase + (uint32_t)(it % 3) * STB32;

        const int nf = it + 2;
        if (nf < nch) {
            const int k0 = nf * CH32;
            fill_stage<CH32>(sbase + (uint32_t)(nf % 3) * STB32,
                             Aht + k0, Alt + k0, Bht + k0, Blt + k0, K, tid);
        }

        #pragma unroll
        for (int ks = 0; ks < KS; ++ks) {
            const int ko = ks * 16;
            uint32_t ah[2][4], al[2][4], bb[4][4];
            uint32_t aoff[2], boff[4];
            #pragma unroll
            for (int mi = 0; mi < 2; ++mi) {
                aoff[mi] = swz<CH32>((uint32_t)((wm + mi * 16 + rr + (qq & 1) * 8) * ROWB
                                                + (ko + (qq >> 1) * 8) * 2));
                ldm_x4(ah[mi], st + aoff[mi]);
                ldm_x4(al[mi], st + MATB + aoff[mi]);
            }
            #pragma unroll
            for (int bi = 0; bi < 4; ++bi) {
                boff[bi] = swz<CH32>((uint32_t)((wn + bi * 16 + rr + (qq >> 1) * 8) * ROWB
                                                + (ko + (qq & 1) * 8) * 2));
                ldm_x4(bb[bi], st + 2 * MATB + boff[bi]);
            }
            #pragma unroll
            for (int mi = 0; mi < 2; ++mi)
                #pragma unroll
                for (int ni = 0; ni < 8; ++ni)
                    mma_bf16(acc[mi][ni], ah[mi],
                             bb[ni >> 1][(ni & 1) * 2], bb[ni >> 1][(ni & 1) * 2 + 1]);
            #pragma unroll
            for (int mi = 0; mi < 2; ++mi)
                #pragma unroll
                for (int ni = 0; ni < 8; ++ni)
                    mma_bf16(acc[mi][ni], al[mi],
                             bb[ni >> 1][(ni & 1) * 2], bb[ni >> 1][(ni & 1) * 2 + 1]);
            #pragma unroll
            for (int bi = 0; bi < 4; ++bi)
                ldm_x4(bb[bi], st + 3 * MATB + boff[bi]);
            #pragma unroll
            for (int mi = 0; mi < 2; ++mi)
                #pragma unroll
                for (int ni = 0; ni < 8; ++ni)
                    mma_bf16(acc[mi][ni], ah[mi],
                             bb[ni >> 1][(ni & 1) * 2], bb[ni >> 1][(ni & 1) * 2 + 1]);
        }
    }

    const int g  = lane >> 2;
    const int t4 = lane & 3;
    #pragma unroll
    for (int mi = 0; mi < 2; ++mi) {
        const int row = m0 + wm + mi * 16 + g;
        #pragma unroll
        for (int ni = 0; ni < 8; ++ni) {
            const int col = n0 + wn + ni * 8 + t4 * 2;
            float b0 = 0.0f, b1 = 0.0f;
            if (bias) { b0 = bias[col]; b1 = bias[col + 1]; }
            const float v00 = acc[mi][ni][0] + b0, v01 = acc[mi][ni][1] + b1;
            const float v10 = acc[mi][ni][2] + b0, v11 = acc[mi][ni][3] + b1;
            if (Cf) {
                float* cg = Cf + bz * sC;
                *reinterpret_cast<float2*>(&cg[(long long)row * N + col])
                    = make_float2(v00, v01);
                *reinterpret_cast<float2*>(&cg[(long long)(row + 8) * N + col])
                    = make_float2(v10, v11);
            }
            if (Ch) {
                uint32_t h, l;
                split2(v00, v01, h, l);
                *reinterpret_cast<uint32_t*>(&Ch[bz * sC + (long long)row * N + col]) = h;
                *reinterpret_cast<uint32_t*>(&Cl[bz * sC + (long long)row * N + col]) = l;
                split2(v10, v11, h, l);
                *reinterpret_cast<uint32_t*>(&Ch[bz * sC + (long long)(row + 8) * N + col]) = h;
                *reinterpret_cast<uint32_t*>(&Cl[bz * sC + (long long)(row + 8) * N + col]) = l;
            }
        }
    }
}

// ---------------------------------------------------------------------------
// fp16 aggregation GEMM, 1-term: C = Ah * B. Chunk 64 (SW128), 3 stages.
// Stage = Ah 16K | B 16K = 32 KB -> 96 KB ring -> 2 CTAs/SM.
// ---------------------------------------------------------------------------
#define STBA (2 * 16384)
#define SMAGG (3 * STBA)

__device__ __forceinline__ void fill_stage_agg(uint32_t st,
    const __half* __restrict__ ah, const __half* __restrict__ bp,
    int K, int tid)
{
    #pragma unroll
    for (int i = 0; i < 4; ++i) {
        const int id  = tid + (i << 8);
        const int row = id >> 3, g = id & 7;
        const long long goff = (long long)row * K + (g << 3);
        const uint32_t so = sw128((uint32_t)((row << 7) + (g << 4)));
        cpa16(st + so,          ah + goff);
        cpa16(st + 16384 + so,  bp + goff);
    }
    cp_commit();
}

__global__ __launch_bounds__(256, 2) void hgemm_agg_f16(
    const __half* __restrict__ Ah, const __half* __restrict__ Bp,
    float* __restrict__ Cf,
    int M, int N, int K,
    long long sA, long long sB, long long sC)
{
    extern __shared__ char smem[];
    const uint32_t sbase = smem_u32(smem);
    const int tid  = threadIdx.x;
    const int lane = tid & 31;
    const int wid  = tid >> 5;

    const int bz = blockIdx.z;
    const int m0 = blockIdx.y * 128;
    const int n0 = blockIdx.x * 128;

    const __half* Aht = Ah + bz * sA + (long long)m0 * K;
    const __half* Bt  = Bp + bz * sB + (long long)n0 * K;

    const int wm = (wid & 3) * 32;
    const int wn = (wid >> 2) * 64;
    const int qq = lane >> 3;
    const int rr = lane & 7;

    float acc[2][8][4];
    #pragma unroll
    for (int mi = 0; mi < 2; mi++)
        #pragma unroll
        for (int ni = 0; ni < 8; ni++)
            #pragma unroll
            for (int c = 0; c < 4; c++) acc[mi][ni][c] = 0.0f;

    const int nch = K / 64;

    fill_stage_agg(sbase, Aht, Bt, K, tid);
    fill_stage_agg(sbase + STBA, Aht + 64, Bt + 64, K, tid);

    for (int it = 0; it < nch; ++it) {
        if (it + 1 < nch) cp_wait<1>(); else cp_wait<0>();
        __syncthreads();

        const uint32_t st = sbase + (uint32_t)(it % 3) * STBA;

        const int nf = it + 2;
        if (nf < nch) {
            const int k0 = nf * 64;
            fill_stage_agg(sbase + (uint32_t)(nf % 3) * STBA,
                           Aht + k0, Bt + k0, K, tid);
        }

        #pragma unroll
        for (int ks = 0; ks < 4; ++ks) {
            const int ko = ks * 16;
            uint32_t ah[2][4], bb[4][4];
            #pragma unroll
            for (int mi = 0; mi < 2; ++mi) {
                const uint32_t aoff =
                    sw128((uint32_t)((wm + mi * 16 + rr + (qq & 1) * 8) * 128
                                     + (ko + (qq >> 1) * 8) * 2));
                ldm_x4(ah[mi], st + aoff);
            }
            #pragma unroll
            for (int bi = 0; bi < 4; ++bi) {
                const uint32_t boff =
                    sw128((uint32_t)((wn + bi * 16 + rr + (qq >> 1) * 8) * 128
                                     + (ko + (qq & 1) * 8) * 2));
                ldm_x4(bb[bi], st + 16384 + boff);
            }
            #pragma unroll
            for (int mi = 0; mi < 2; ++mi)
                #pragma unroll
                for (int ni = 0; ni < 8; ++ni)
                    mma_f16(acc[mi][ni], ah[mi],
                            bb[ni >> 1][(ni & 1) * 2], bb[ni >> 1][(ni & 1) * 2 + 1]);
        }
    }

    const int g  = lane >> 2;
    const int t4 = lane & 3;
    float* cg = Cf + bz * sC;
    #pragma unroll
    for (int mi = 0; mi < 2; ++mi) {
        const int row = m0 + wm + mi * 16 + g;
        #pragma unroll
        for (int ni = 0; ni < 8; ++ni) {
            const int col = n0 + wn + ni * 8 + t4 * 2;
            *reinterpret_cast<float2*>(&cg[(long long)row * N + col])
                = make_float2(acc[mi][ni][0], acc[mi][ni][1]);
            *reinterpret_cast<float2*>(&cg[(long long)(row + 8) * N + col])
                = make_float2(acc[mi][ni][2], acc[mi][ni][3]);
        }
    }
}

// ---------------------------------------------------------------------------
// Single-pass row softmax WITHOUT max subtraction (|energy| <= ~70).
// Writes normalized attention as single fp16.
// ---------------------------------------------------------------------------
__global__ __launch_bounds__(256) void softmax_f16_kernel(
    const float* __restrict__ en, __half* __restrict__ out)
{
    const size_t base = (size_t)blockIdx.x * NN;
    const int tid = threadIdx.x;
    const float4* src = reinterpret_cast<const float4*>(en + base);
    __shared__ float red[8];

    float4 v0 = src[tid];
    float4 v1 = src[tid + 256];

    v0.x = __expf(v0.x); v0.y = __expf(v0.y);
    v0.z = __expf(v0.z); v0.w = __expf(v0.w);
    v1.x = __expf(v1.x); v1.y = __expf(v1.y);
    v1.z = __expf(v1.z); v1.w = __expf(v1.w);

    float s = v0.x + v0.y + v0.z + v0.w + v1.x + v1.y + v1.z + v1.w;
    #pragma unroll
    for (int o = 16; o; o >>= 1) s += __shfl_xor_sync(0xffffffffu, s, o);
    if ((tid & 31) == 0) red[tid >> 5] = s;
    __syncthreads();
    s = red[0];
    #pragma unroll
    for (int w = 1; w < 8; ++w) s += red[w];
    const float inv = 1.0f / s;

    uint2* po = reinterpret_cast<uint2*>(out + base);
    uint32_t p0, p1;
    asm("cvt.rn.f16x2.f32 %0, %1, %2;" : "=r"(p0) : "f"(v0.y * inv), "f"(v0.x * inv));
    asm("cvt.rn.f16x2.f32 %0, %1, %2;" : "=r"(p1) : "f"(v0.w * inv), "f"(v0.z * inv));
    po[tid] = make_uint2(p0, p1);
    asm("cvt.rn.f16x2.f32 %0, %1, %2;" : "=r"(p0) : "f"(v1.y * inv), "f"(v1.x * inv));
    asm("cvt.rn.f16x2.f32 %0, %1, %2;" : "=r"(p1) : "f"(v1.w * inv), "f"(v1.z * inv));
    po[tid + 256] = make_uint2(p0, p1);
}

// ---------------------------------------------------------------------------
// Launch: per-batch energy->softmax->agg chains on two streams (fork/join).
// Stream + events are created on the FIRST (non-captured) correctness call;
// the captured call only records/waits them (standard multi-stream capture).
// ---------------------------------------------------------------------------
static cudaStream_t g_s2 = nullptr;
static cudaEvent_t  g_evFork = nullptr;
static cudaEvent_t  g_evJoin = nullptr;

extern "C" void kernel_launch(void* const* d_in, const int* in_sizes, int n_in,
                              void* d_out, int out_size)
{
    const float* logits   = (const float*)d_in[0];  // [B,L,N]
    const float* features = (const float*)d_in[1];  // [B,N,C]
    const float* Wq       = (const float*)d_in[2];  // [D,C]
    const float* bq       = (const float*)d_in[3];  // [D]
    const float* Wk       = (const float*)d_in[4];  // [D,C]
    const float* bk       = (const float*)d_in[5];  // [D]
    float* out            = (float*)d_out;          // [B,L,N]

    if (!g_s2) {
        cudaStreamCreateWithFlags(&g_s2, cudaStreamNonBlocking);
        cudaEventCreateWithFlags(&g_evFork, cudaEventDisableTiming);
        cudaEventCreateWithFlags(&g_evJoin, cudaEventDisableTiming);
    }

    __nv_bfloat16 *feat_h, *feat_l;
    __half *log_h, *attn;
    __nv_bfloat16 *wq_h, *wq_l, *wk_h, *wk_l;
    __nv_bfloat16 *q_h, *q_l, *k_h, *k_l;
    float* energy;
    cudaGetSymbolAddress((void**)&feat_h, g_feat_h);
    cudaGetSymbolAddress((void**)&feat_l, g_feat_l);
    cudaGetSymbolAddress((void**)&log_h,  g_log_h);
    cudaGetSymbolAddress((void**)&wq_h,   g_wq_h);
    cudaGetSymbolAddress((void**)&wq_l,   g_wq_l);
    cudaGetSymbolAddress((void**)&wk_h,   g_wk_h);
    cudaGetSymbolAddress((void**)&wk_l,   g_wk_l);
    cudaGetSymbolAddress((void**)&q_h,    g_q_h);
    cudaGetSymbolAddress((void**)&q_l,    g_q_l);
    cudaGetSymbolAddress((void**)&k_h,    g_k_h);
    cudaGetSymbolAddress((void**)&k_l,    g_k_l);
    cudaGetSymbolAddress((void**)&attn,   g_attn);
    cudaGetSymbolAddress((void**)&energy, g_energy);

    cudaFuncSetAttribute(hgemm_nt,
                         cudaFuncAttributeMaxDynamicSharedMemorySize, SM32);
    cudaFuncSetAttribute(hgemm_agg_f16,
                         cudaFuncAttributeMaxDynamicSharedMemorySize, SMAGG);

    // 0) one merged split pass over all four inputs (main stream)
    {
        const int total4 = F4C + L4C + 2 * W4C;
        split_all_kernel<<<(total4 + 255) / 256, 256>>>(
            (const float4*)features, (const float4*)logits,
            (const float4*)Wq, (const float4*)Wk,
            (uint2*)feat_h, (uint2*)feat_l,
            (uint2*)log_h,
            (uint2*)wq_h,   (uint2*)wq_l,
            (uint2*)wk_h,   (uint2*)wk_l);
    }

    // 1) Both projections in ONE launch (blockIdx.x selects Wq/Wk set)
    hgemm_nt<<<dim3(2, (BB * NN) / 128, 1), 256, SM32>>>(
        feat_h, feat_l, wq_h, wq_l, wk_h, wk_l,
        nullptr, q_h, q_l, k_h, k_l, bq, bk,
        BB * NN, DD, CC, 0, 0, 0);

    // fork: bring g_s2 into the capture after proj
    cudaEventRecord(g_evFork, 0);
    cudaStreamWaitEvent(g_s2, g_evFork, 0);

    // 2-4) Per-batch chains, alternating streams (independent across batches)
    for (int b = 0; b < BB; ++b) {
        cudaStream_t st = (b & 1) ? g_s2 : (cudaStream_t)0;
        const long long qo = (long long)b * NN * DD;
        const size_t   eo = (size_t)b * NN * NN;
        const long long lo = (long long)b * LL * NN;

        // energy(b): Q[2048,128] @ K^T -> fp32 (chunk 32, 3 stages)
        hgemm_nt<<<dim3(NN / 128, NN / 128, 1), 256, SM32, st>>>(
            q_h + qo, q_l + qo, k_h + qo, k_l + qo, nullptr, nullptr,
            energy + eo, nullptr, nullptr, nullptr, nullptr, nullptr, nullptr,
            NN, NN, DD, 0, 0, 0);

        // softmax(b) -> attn fp16
        softmax_f16_kernel<<<NN, 256, 0, st>>>(energy + eo, attn + eo);

        // agg(b): out[l,m] = sum_n logits[l,n]*attn[m,n]
        hgemm_agg_f16<<<dim3(NN / 128, LL / 128, 1), 256, SMAGG, st>>>(
            log_h + lo, attn + eo, out + lo,
            LL, NN, NN, 0, 0, 0);
    }

    // join: main stream waits for g_s2's batches
    cudaEventRecord(g_evJoin, g_s2);
    cudaStreamWaitEvent((cudaStream_t)0, g_evJoin, 0);
}

// round 17
// speedup vs baseline: 1.0842x; 1.0842x over previous
#include <cuda_runtime.h>
#include <cuda_bf16.h>
#include <cuda_fp16.h>
#include <math.h>
#include <stdint.h>

// Problem shape constants
#define BB 8
#define LL 512
#define NN 2048
#define CC 1024
#define DD 128

// ---------------------------------------------------------------------------
// Scratch (device globals — no allocations allowed)
// ---------------------------------------------------------------------------
__device__ __align__(16) __nv_bfloat16 g_feat_h[BB * NN * CC];   // 32 MB
__device__ __align__(16) __nv_bfloat16 g_feat_l[BB * NN * CC];
__device__ __align__(16) __half        g_log_h[BB * LL * NN];    // fp16 hi only
__device__ __align__(16) __nv_bfloat16 g_wq_h[DD * CC];
__device__ __align__(16) __nv_bfloat16 g_wq_l[DD * CC];
__device__ __align__(16) __nv_bfloat16 g_wk_h[DD * CC];
__device__ __align__(16) __nv_bfloat16 g_wk_l[DD * CC];
__device__ __align__(16) __nv_bfloat16 g_q_h[BB * NN * DD];      // 4 MB
__device__ __align__(16) __nv_bfloat16 g_q_l[BB * NN * DD];
__device__ __align__(16) __nv_bfloat16 g_k_h[BB * NN * DD];
__device__ __align__(16) __nv_bfloat16 g_k_l[BB * NN * DD];
__device__ __align__(16) float g_energy[(size_t)BB * NN * NN];   // 128 MB
__device__ __align__(16) __half g_attn[(size_t)BB * NN * NN];    // 64 MB fp16

// ---------------------------------------------------------------------------
// Helpers (family-portable PTX only: ldmatrix / mma.sync / cp.async)
// ---------------------------------------------------------------------------
__device__ __forceinline__ uint32_t smem_u32(const void* p) {
    uint32_t a;
    asm("{ .reg .u64 t; cvta.to.shared.u64 t, %1; cvt.u32.u64 %0, t; }"
        : "=r"(a) : "l"(p));
    return a;
}

__device__ __forceinline__ void ldm_x4(uint32_t r[4], uint32_t addr) {
    asm volatile("ldmatrix.sync.aligned.m8n8.x4.shared.b16 {%0,%1,%2,%3}, [%4];"
                 : "=r"(r[0]), "=r"(r[1]), "=r"(r[2]), "=r"(r[3])
                 : "r"(addr));
}

__device__ __forceinline__ void mma_bf16(float d[4], const uint32_t a[4],
                                         uint32_t b0, uint32_t b1) {
    asm volatile(
        "mma.sync.aligned.m16n8k16.row.col.f32.bf16.bf16.f32 "
        "{%0,%1,%2,%3}, {%4,%5,%6,%7}, {%8,%9}, {%0,%1,%2,%3};"
        : "+f"(d[0]), "+f"(d[1]), "+f"(d[2]), "+f"(d[3])
        : "r"(a[0]), "r"(a[1]), "r"(a[2]), "r"(a[3]), "r"(b0), "r"(b1));
}

__device__ __forceinline__ void mma_f16(float d[4], const uint32_t a[4],
                                        uint32_t b0, uint32_t b1) {
    asm volatile(
        "mma.sync.aligned.m16n8k16.row.col.f32.f16.f16.f32 "
        "{%0,%1,%2,%3}, {%4,%5,%6,%7}, {%8,%9}, {%0,%1,%2,%3};"
        : "+f"(d[0]), "+f"(d[1]), "+f"(d[2]), "+f"(d[3])
        : "r"(a[0]), "r"(a[1]), "r"(a[2]), "r"(a[3]), "r"(b0), "r"(b1));
}

__device__ __forceinline__ void cpa16(uint32_t dst, const void* src) {
    asm volatile("cp.async.cg.shared.global [%0], [%1], 16;"
                 :: "r"(dst), "l"(src));
}
__device__ __forceinline__ void cp_commit() {
    asm volatile("cp.async.commit_group;" ::: "memory");
}
template <int N>
__device__ __forceinline__ void cp_wait() {
    asm volatile("cp.async.wait_group %0;" :: "n"(N) : "memory");
}

__device__ __forceinline__ uint32_t sw128(uint32_t off) {
    return off ^ ((off >> 3) & 0x70);
}

// Fast split fp32 -> (bf16 hi rtz, bf16 lo rn) packed pairs.
__device__ __forceinline__ void split2(float x0, float x1, uint32_t& hi, uint32_t& lo) {
    const uint32_t xi0 = __float_as_uint(x0);
    const uint32_t xi1 = __float_as_uint(x1);
    asm("prmt.b32 %0, %1, %2, 0x7632;" : "=r"(hi) : "r"(xi0), "r"(xi1));
    const float t0 = __uint_as_float(xi0 & 0xFFFF0000u);
    const float t1 = __uint_as_float(xi1 & 0xFFFF0000u);
    const float l0 = x0 - t0;
    const float l1 = x1 - t1;
    asm("cvt.rn.bf16x2.f32 %0, %1, %2;" : "=r"(lo) : "f"(l1), "f"(l0));
}

// ---------------------------------------------------------------------------
// Merged elementwise split: feat/Wq/Wk -> bf16 hi/lo ; logits -> fp16 (hi only)
// ---------------------------------------------------------------------------
#define F4C (BB * NN * CC / 4)
#define L4C (BB * LL * NN / 4)
#define W4C (DD * CC / 4)

__global__ __launch_bounds__(256) void split_all_kernel(
    const float4* __restrict__ feat, const float4* __restrict__ logi,
    const float4* __restrict__ wq,   const float4* __restrict__ wk,
    uint2* __restrict__ fh, uint2* __restrict__ fl,
    uint2* __restrict__ lh,
    uint2* __restrict__ qh, uint2* __restrict__ ql,
    uint2* __restrict__ kh, uint2* __restrict__ kl)
{
    const int i = blockIdx.x * 256 + threadIdx.x;
    uint32_t h0, l0, h1, l1;
    if (i < F4C) {
        float4 v = feat[i];
        split2(v.x, v.y, h0, l0); split2(v.z, v.w, h1, l1);
        fh[i] = make_uint2(h0, h1); fl[i] = make_uint2(l0, l1);
    } else if (i < F4C + L4C) {
        const int j = i - F4C;
        float4 v = logi[j];
        asm("cvt.rn.f16x2.f32 %0, %1, %2;" : "=r"(h0) : "f"(v.y), "f"(v.x));
        asm("cvt.rn.f16x2.f32 %0, %1, %2;" : "=r"(h1) : "f"(v.w), "f"(v.z));
        lh[j] = make_uint2(h0, h1);
    } else if (i < F4C + L4C + W4C) {
        const int j = i - F4C - L4C;
        float4 v = wq[j];
        split2(v.x, v.y, h0, l0); split2(v.z, v.w, h1, l1);
        qh[j] = make_uint2(h0, h1); ql[j] = make_uint2(l0, l1);
    } else {
        const int j = i - F4C - L4C - W4C;
        float4 v = wk[j];
        split2(v.x, v.y, h0, l0); split2(v.z, v.w, h1, l1);
        kh[j] = make_uint2(h0, h1); kl[j] = make_uint2(l0, l1);
    }
}

// ---------------------------------------------------------------------------
// bf16 HMMA NT GEMM, 3-term split (proj + energy).
// CHUNK=32 (SW64 rows), 3 stages, 96KB -> 2 CTAs/SM via launch_bounds(256,2).
// 256 threads = 8 warps (4m x 2n), warp tile 32x64.
// Dual-B mode (Bh2 != 0): blockIdx.x selects {B,C,bias} set, n0 = 0.
// ---------------------------------------------------------------------------
template <int CHUNK>
__device__ __forceinline__ uint32_t swz(uint32_t off) {
    if (CHUNK == 64) return off ^ ((off >> 3) & 0x70);   // SW128 (128B rows)
    else             return off ^ ((off >> 3) & 0x30);   // SW64  (64B rows)
}

template <int CHUNK>
__device__ __forceinline__ void fill_stage(uint32_t st,
    const __nv_bfloat16* __restrict__ ah, const __nv_bfloat16* __restrict__ al,
    const __nv_bfloat16* __restrict__ bh, const __nv_bfloat16* __restrict__ bl,
    int K, int tid)
{
    constexpr int ROWB = CHUNK * 2;          // bytes per smem row
    constexpr int MATB = 128 * ROWB;         // bytes per matrix tile
    constexpr int G    = CHUNK / 8;          // 16B groups per row
    constexpr int ITER = CHUNK / 16;         // 128*G/256 per-thread loads/matrix
    #pragma unroll
    for (int i = 0; i < ITER; ++i) {
        const int id  = tid + (i << 8);
        const int row = id / G, g = id % G;
        const long long goff = (long long)row * K + (g << 3);
        const uint32_t so = swz<CHUNK>((uint32_t)(row * ROWB + (g << 4)));
        cpa16(st + so,            ah + goff);
        cpa16(st + MATB + so,     al + goff);
        cpa16(st + 2 * MATB + so, bh + goff);
        cpa16(st + 3 * MATB + so, bl + goff);
    }
    cp_commit();
}

#define CH32 32
#define STB32 (4 * 128 * (CH32 * 2))        // 32768
#define SM32  (3 * STB32)                   // 98304

__global__ __launch_bounds__(256, 2) void hgemm_nt(
    const __nv_bfloat16* __restrict__ Ah, const __nv_bfloat16* __restrict__ Al,
    const __nv_bfloat16* __restrict__ pBh, const __nv_bfloat16* __restrict__ pBl,
    const __nv_bfloat16* __restrict__ Bh2, const __nv_bfloat16* __restrict__ Bl2,
    float* __restrict__ Cf,
    __nv_bfloat16* __restrict__ pCh, __nv_bfloat16* __restrict__ pCl,
    __nv_bfloat16* __restrict__ Ch2, __nv_bfloat16* __restrict__ Cl2,
    const float* __restrict__ pbias, const float* __restrict__ bias2,
    int M, int N, int K,
    long long sA, long long sB, long long sC)
{
    constexpr int ROWB = CH32 * 2;          // 64
    constexpr int MATB = 128 * ROWB;        // 8192
    constexpr int KS   = CH32 / 16;         // 2

    extern __shared__ char smem[];
    const uint32_t sbase = smem_u32(smem);
    const int tid  = threadIdx.x;
    const int lane = tid & 31;
    const int wid  = tid >> 5;

    const int bz = blockIdx.z;
    const int m0 = blockIdx.y * 128;

    const __nv_bfloat16* Bh = pBh;
    const __nv_bfloat16* Bl = pBl;
    __nv_bfloat16* Ch = pCh;
    __nv_bfloat16* Cl = pCl;
    const float* bias = pbias;
    int n0;
    if (Bh2) {
        n0 = 0;
        if (blockIdx.x) { Bh = Bh2; Bl = Bl2; Ch = Ch2; Cl = Cl2; bias = bias2; }
    } else {
        n0 = blockIdx.x * 128;
    }

    const __nv_bfloat16* Aht = Ah + bz * sA + (long long)m0 * K;
    const __nv_bfloat16* Alt = Al + bz * sA + (long long)m0 * K;
    const __nv_bfloat16* Bht = Bh + bz * sB + (long long)n0 * K;
    const __nv_bfloat16* Blt = Bl + bz * sB + (long long)n0 * K;

    const int wm = (wid & 3) * 32;
    const int wn = (wid >> 2) * 64;
    const int qq = lane >> 3;
    const int rr = lane & 7;

    float acc[2][8][4];
    #pragma unroll
    for (int mi = 0; mi < 2; mi++)
        #pragma unroll
        for (int ni = 0; ni < 8; ni++)
            #pragma unroll
            for (int c = 0; c < 4; c++) acc[mi][ni][c] = 0.0f;

    const int nch = K / CH32;

    fill_stage<CH32>(sbase, Aht, Alt, Bht, Blt, K, tid);
    fill_stage<CH32>(sbase + STB32, Aht + CH32, Alt + CH32,
                     Bht + CH32, Blt + CH32, K, tid);

    for (int it = 0; it < nch; ++it) {
        if (it + 1 < nch) cp_wait<1>(); else cp_wait<0>();
        __syncthreads();

        const uint32_t st = sbase + (uint32_t)(it % 3) * STB32;

        const int nf = it + 2;
        if (nf < nch) {
            const int k0 = nf * CH32;
            fill_stage<CH32>(sbase + (uint32_t)(nf % 3) * STB32,
                             Aht + k0, Alt + k0, Bht + k0, Blt + k0, K, tid);
        }

        #pragma unroll
        for (int ks = 0; ks < KS; ++ks) {
            const int ko = ks * 16;
            uint32_t ah[2][4], al[2][4], bb[4][4];
            uint32_t aoff[2], boff[4];
            #pragma unroll
            for (int mi = 0; mi < 2; ++mi) {
                aoff[mi] = swz<CH32>((uint32_t)((wm + mi * 16 + rr + (qq & 1) * 8) * ROWB
                                                + (ko + (qq >> 1) * 8) * 2));
                ldm_x4(ah[mi], st + aoff[mi]);
                ldm_x4(al[mi], st + MATB + aoff[mi]);
            }
            #pragma unroll
            for (int bi = 0; bi < 4; ++bi) {
                boff[bi] = swz<CH32>((uint32_t)((wn + bi * 16 + rr + (qq >> 1) * 8) * ROWB
                                                + (ko + (qq & 1) * 8) * 2));
                ldm_x4(bb[bi], st + 2 * MATB + boff[bi]);
            }
            #pragma unroll
            for (int mi = 0; mi < 2; ++mi)
                #pragma unroll
                for (int ni = 0; ni < 8; ++ni)
                    mma_bf16(acc[mi][ni], ah[mi],
                             bb[ni >> 1][(ni & 1) * 2], bb[ni >> 1][(ni & 1) * 2 + 1]);
            #pragma unroll
            for (int mi = 0; mi < 2; ++mi)
                #pragma unroll
                for (int ni = 0; ni < 8; ++ni)
                    mma_bf16(acc[mi][ni], al[mi],
                             bb[ni >> 1][(ni & 1) * 2], bb[ni >> 1][(ni & 1) * 2 + 1]);
            #pragma unroll
            for (int bi = 0; bi < 4; ++bi)
                ldm_x4(bb[bi], st + 3 * MATB + boff[bi]);
            #pragma unroll
            for (int mi = 0; mi < 2; ++mi)
                #pragma unroll
                for (int ni = 0; ni < 8; ++ni)
                    mma_bf16(acc[mi][ni], ah[mi],
                             bb[ni >> 1][(ni & 1) * 2], bb[ni >> 1][(ni & 1) * 2 + 1]);
        }
    }

    const int g  = lane >> 2;
    const int t4 = lane & 3;
    #pragma unroll
    for (int mi = 0; mi < 2; ++mi) {
        const int row = m0 + wm + mi * 16 + g;
        #pragma unroll
        for (int ni = 0; ni < 8; ++ni) {
            const int col = n0 + wn + ni * 8 + t4 * 2;
            float b0 = 0.0f, b1 = 0.0f;
            if (bias) { b0 = bias[col]; b1 = bias[col + 1]; }
            const float v00 = acc[mi][ni][0] + b0, v01 = acc[mi][ni][1] + b1;
            const float v10 = acc[mi][ni][2] + b0, v11 = acc[mi][ni][3] + b1;
            if (Cf) {
                float* cg = Cf + bz * sC;
                *reinterpret_cast<float2*>(&cg[(long long)row * N + col])
                    = make_float2(v00, v01);
                *reinterpret_cast<float2*>(&cg[(long long)(row + 8) * N + col])
                    = make_float2(v10, v11);
            }
            if (Ch) {
                uint32_t h, l;
                split2(v00, v01, h, l);
                *reinterpret_cast<uint32_t*>(&Ch[bz * sC + (long long)row * N + col]) = h;
                *reinterpret_cast<uint32_t*>(&Cl[bz * sC + (long long)row * N + col]) = l;
                split2(v10, v11, h, l);
                *reinterpret_cast<uint32_t*>(&Ch[bz * sC + (long long)(row + 8) * N + col]) = h;
                *reinterpret_cast<uint32_t*>(&Cl[bz * sC + (long long)(row + 8) * N + col]) = l;
            }
        }
    }
}

// ---------------------------------------------------------------------------
// fp16 aggregation GEMM, 1-term: C = Ah * B. Chunk 64 (SW128), 3 stages.
// Stage = Ah 16K | B 16K = 32 KB -> 96 KB ring -> 2 CTAs/SM.
// ---------------------------------------------------------------------------
#define STBA (2 * 16384)
#define SMAGG (3 * STBA)

__device__ __forceinline__ void fill_stage_agg(uint32_t st,
    const __half* __restrict__ ah, const __half* __restrict__ bp,
    int K, int tid)
{
    #pragma unroll
    for (int i = 0; i < 4; ++i) {
        const int id  = tid + (i << 8);
        const int row = id >> 3, g = id & 7;
        const long long goff = (long long)row * K + (g << 3);
        const uint32_t so = sw128((uint32_t)((row << 7) + (g << 4)));
        cpa16(st + so,          ah + goff);
        cpa16(st + 16384 + so,  bp + goff);
    }
    cp_commit();
}

__global__ __launch_bounds__(256, 2) void hgemm_agg_f16(
    const __half* __restrict__ Ah, const __half* __restrict__ Bp,
    float* __restrict__ Cf,
    int M, int N, int K,
    long long sA, long long sB, long long sC)
{
    extern __shared__ char smem[];
    const uint32_t sbase = smem_u32(smem);
    const int tid  = threadIdx.x;
    const int lane = tid & 31;
    const int wid  = tid >> 5;

    const int bz = blockIdx.z;
    const int m0 = blockIdx.y * 128;
    const int n0 = blockIdx.x * 128;

    const __half* Aht = Ah + bz * sA + (long long)m0 * K;
    const __half* Bt  = Bp + bz * sB + (long long)n0 * K;

    const int wm = (wid & 3) * 32;
    const int wn = (wid >> 2) * 64;
    const int qq = lane >> 3;
    const int rr = lane & 7;

    float acc[2][8][4];
    #pragma unroll
    for (int mi = 0; mi < 2; mi++)
        #pragma unroll
        for (int ni = 0; ni < 8; ni++)
            #pragma unroll
            for (int c = 0; c < 4; c++) acc[mi][ni][c] = 0.0f;

    const int nch = K / 64;

    fill_stage_agg(sbase, Aht, Bt, K, tid);
    fill_stage_agg(sbase + STBA, Aht + 64, Bt + 64, K, tid);

    for (int it = 0; it < nch; ++it) {
        if (it + 1 < nch) cp_wait<1>(); else cp_wait<0>();
        __syncthreads();

        const uint32_t st = sbase + (uint32_t)(it % 3) * STBA;

        const int nf = it + 2;
        if (nf < nch) {
            const int k0 = nf * 64;
            fill_stage_agg(sbase + (uint32_t)(nf % 3) * STBA,
                           Aht + k0, Bt + k0, K, tid);
        }

        #pragma unroll
        for (int ks = 0; ks < 4; ++ks) {
            const int ko = ks * 16;
            uint32_t ah[2][4], bb[4][4];
            #pragma unroll
            for (int mi = 0; mi < 2; ++mi) {
                const uint32_t aoff =
                    sw128((uint32_t)((wm + mi * 16 + rr + (qq & 1) * 8) * 128
                                     + (ko + (qq >> 1) * 8) * 2));
                ldm_x4(ah[mi], st + aoff);
            }
            #pragma unroll
            for (int bi = 0; bi < 4; ++bi) {
                const uint32_t boff =
                    sw128((uint32_t)((wn + bi * 16 + rr + (qq >> 1) * 8) * 128
                                     + (ko + (qq & 1) * 8) * 2));
                ldm_x4(bb[bi], st + 16384 + boff);
            }
            #pragma unroll
            for (int mi = 0; mi < 2; ++mi)
                #pragma unroll
                for (int ni = 0; ni < 8; ++ni)
                    mma_f16(acc[mi][ni], ah[mi],
                            bb[ni >> 1][(ni & 1) * 2], bb[ni >> 1][(ni & 1) * 2 + 1]);
        }
    }

    const int g  = lane >> 2;
    const int t4 = lane & 3;
    float* cg = Cf + bz * sC;
    #pragma unroll
    for (int mi = 0; mi < 2; ++mi) {
        const int row = m0 + wm + mi * 16 + g;
        #pragma unroll
        for (int ni = 0; ni < 8; ++ni) {
            const int col = n0 + wn + ni * 8 + t4 * 2;
            *reinterpret_cast<float2*>(&cg[(long long)row * N + col])
                = make_float2(acc[mi][ni][0], acc[mi][ni][1]);
            *reinterpret_cast<float2*>(&cg[(long long)(row + 8) * N + col])
                = make_float2(acc[mi][ni][2], acc[mi][ni][3]);
        }
    }
}

// ---------------------------------------------------------------------------
// Single-pass row softmax WITHOUT max subtraction (|energy| <= ~70).
// Writes normalized attention as single fp16.
// ---------------------------------------------------------------------------
__global__ __launch_bounds__(256) void softmax_f16_kernel(
    const float* __restrict__ en, __half* __restrict__ out)
{
    const size_t base = (size_t)blockIdx.x * NN;
    const int tid = threadIdx.x;
    const float4* src = reinterpret_cast<const float4*>(en + base);
    __shared__ float red[8];

    float4 v0 = src[tid];
    float4 v1 = src[tid + 256];

    v0.x = __expf(v0.x); v0.y = __expf(v0.y);
    v0.z = __expf(v0.z); v0.w = __expf(v0.w);
    v1.x = __expf(v1.x); v1.y = __expf(v1.y);
    v1.z = __expf(v1.z); v1.w = __expf(v1.w);

    float s = v0.x + v0.y + v0.z + v0.w + v1.x + v1.y + v1.z + v1.w;
    #pragma unroll
    for (int o = 16; o; o >>= 1) s += __shfl_xor_sync(0xffffffffu, s, o);
    if ((tid & 31) == 0) red[tid >> 5] = s;
    __syncthreads();
    s = red[0];
    #pragma unroll
    for (int w = 1; w < 8; ++w) s += red[w];
    const float inv = 1.0f / s;

    uint2* po = reinterpret_cast<uint2*>(out + base);
    uint32_t p0, p1;
    asm("cvt.rn.f16x2.f32 %0, %1, %2;" : "=r"(p0) : "f"(v0.y * inv), "f"(v0.x * inv));
    asm("cvt.rn.f16x2.f32 %0, %1, %2;" : "=r"(p1) : "f"(v0.w * inv), "f"(v0.z * inv));
    po[tid] = make_uint2(p0, p1);
    asm("cvt.rn.f16x2.f32 %0, %1, %2;" : "=r"(p0) : "f"(v1.y * inv), "f"(v1.x * inv));
    asm("cvt.rn.f16x2.f32 %0, %1, %2;" : "=r"(p1) : "f"(v1.w * inv), "f"(v1.z * inv));
    po[tid + 256] = make_uint2(p0, p1);
}

// ---------------------------------------------------------------------------
// Launch: two half-batch chains (4 batches each) on two streams (fork/join).
// Stream + events created on the FIRST (non-captured) correctness call; the
// captured call only records/waits them (standard multi-stream capture).
// ---------------------------------------------------------------------------
static cudaStream_t g_s2 = nullptr;
static cudaEvent_t  g_evFork = nullptr;
static cudaEvent_t  g_evJoin = nullptr;

extern "C" void kernel_launch(void* const* d_in, const int* in_sizes, int n_in,
                              void* d_out, int out_size)
{
    const float* logits   = (const float*)d_in[0];  // [B,L,N]
    const float* features = (const float*)d_in[1];  // [B,N,C]
    const float* Wq       = (const float*)d_in[2];  // [D,C]
    const float* bq       = (const float*)d_in[3];  // [D]
    const float* Wk       = (const float*)d_in[4];  // [D,C]
    const float* bk       = (const float*)d_in[5];  // [D]
    float* out            = (float*)d_out;          // [B,L,N]

    if (!g_s2) {
        cudaStreamCreateWithFlags(&g_s2, cudaStreamNonBlocking);
        cudaEventCreateWithFlags(&g_evFork, cudaEventDisableTiming);
        cudaEventCreateWithFlags(&g_evJoin, cudaEventDisableTiming);
    }

    __nv_bfloat16 *feat_h, *feat_l;
    __half *log_h, *attn;
    __nv_bfloat16 *wq_h, *wq_l, *wk_h, *wk_l;
    __nv_bfloat16 *q_h, *q_l, *k_h, *k_l;
    float* energy;
    cudaGetSymbolAddress((void**)&feat_h, g_feat_h);
    cudaGetSymbolAddress((void**)&feat_l, g_feat_l);
    cudaGetSymbolAddress((void**)&log_h,  g_log_h);
    cudaGetSymbolAddress((void**)&wq_h,   g_wq_h);
    cudaGetSymbolAddress((void**)&wq_l,   g_wq_l);
    cudaGetSymbolAddress((void**)&wk_h,   g_wk_h);
    cudaGetSymbolAddress((void**)&wk_l,   g_wk_l);
    cudaGetSymbolAddress((void**)&q_h,    g_q_h);
    cudaGetSymbolAddress((void**)&q_l,    g_q_l);
    cudaGetSymbolAddress((void**)&k_h,    g_k_h);
    cudaGetSymbolAddress((void**)&k_l,    g_k_l);
    cudaGetSymbolAddress((void**)&attn,   g_attn);
    cudaGetSymbolAddress((void**)&energy, g_energy);

    cudaFuncSetAttribute(hgemm_nt,
                         cudaFuncAttributeMaxDynamicSharedMemorySize, SM32);
    cudaFuncSetAttribute(hgemm_agg_f16,
                         cudaFuncAttributeMaxDynamicSharedMemorySize, SMAGG);

    // 0) one merged split pass over all four inputs (main stream)
    {
        const int total4 = F4C + L4C + 2 * W4C;
        split_all_kernel<<<(total4 + 255) / 256, 256>>>(
            (const float4*)features, (const float4*)logits,
            (const float4*)Wq, (const float4*)Wk,
            (uint2*)feat_h, (uint2*)feat_l,
            (uint2*)log_h,
            (uint2*)wq_h,   (uint2*)wq_l,
            (uint2*)wk_h,   (uint2*)wk_l);
    }

    // 1) Both projections in ONE launch (blockIdx.x selects Wq/Wk set)
    hgemm_nt<<<dim3(2, (BB * NN) / 128, 1), 256, SM32>>>(
        feat_h, feat_l, wq_h, wq_l, wk_h, wk_l,
        nullptr, q_h, q_l, k_h, k_l, bq, bk,
        BB * NN, DD, CC, 0, 0, 0);

    // fork: bring g_s2 into the capture after proj
    cudaEventRecord(g_evFork, 0);
    cudaStreamWaitEvent(g_s2, g_evFork, 0);

    // 2-4) Two half-batch chains (4 batches each), one per stream.
    const int HB = BB / 2;  // 4
    for (int h = 0; h < 2; ++h) {
        cudaStream_t st = h ? g_s2 : (cudaStream_t)0;
        const int b0 = h * HB;
        const long long qo = (long long)b0 * NN * DD;
        const size_t   eo = (size_t)b0 * NN * NN;
        const long long lo = (long long)b0 * LL * NN;

        // energy(half): 4 batches, grid 16x16x4 = 1024 CTAs
        hgemm_nt<<<dim3(NN / 128, NN / 128, HB), 256, SM32, st>>>(
            q_h + qo, q_l + qo, k_h + qo, k_l + qo, nullptr, nullptr,
            energy + eo, nullptr, nullptr, nullptr, nullptr, nullptr, nullptr,
            NN, NN, DD,
            (long long)NN * DD, (long long)NN * DD, (long long)NN * NN);

        // softmax(half): 8192 blocks
        softmax_f16_kernel<<<HB * NN, 256, 0, st>>>(energy + eo, attn + eo);

        // agg(half): grid 16x4x4 = 256 CTAs
        hgemm_agg_f16<<<dim3(NN / 128, LL / 128, HB), 256, SMAGG, st>>>(
            log_h + lo, attn + eo, out + lo,
            LL, NN, NN,
            (long long)LL * NN, (long long)NN * NN, (long long)LL * NN);
    }

    // join: main stream waits for g_s2's half
    cudaEventRecord(g_evJoin, g_s2);
    cudaStreamWaitEvent((cudaStream_t)0, g_evJoin, 0);
}